// round 1
// baseline (speedup 1.0000x reference)
#include <cuda_runtime.h>

#define N_NODES 100000
#define N_EDGES 1600000
#define N_FEAT  256
#define N_HID   64
#define N_CLS   16

// Scratch (device globals: allocation-free, graph-safe)
__device__ float g_h0[N_NODES * N_HID];   // x@W1+b1
__device__ float g_h [N_NODES * N_HID];   // spmm1 output (pre-relu)
__device__ float g_h2[N_NODES * N_CLS];   // relu(h)@W2+b2

// ---------------------------------------------------------------------------
// Zero the scatter targets (g_h and d_out)
// ---------------------------------------------------------------------------
__global__ void k_zero(float* __restrict__ out) {
    int i = blockIdx.x * blockDim.x + threadIdx.x;
    if (i < N_NODES * N_HID) g_h[i] = 0.0f;
    if (i < N_NODES * N_CLS) out[i] = 0.0f;
}

// ---------------------------------------------------------------------------
// GEMM1: g_h0[n][j] = sum_k x[n][k] * W1[k][j] + b1[j]
// Tile: 128 nodes x 64 feats per block, 256 threads, 8x4 per thread, KT=16
// ---------------------------------------------------------------------------
__global__ __launch_bounds__(256) void k_gemm1(const float* __restrict__ x,
                                               const float* __restrict__ W1,
                                               const float* __restrict__ b1) {
    const int TM = 128, KT = 16, PAD = 4;
    __shared__ float xs[KT][TM + PAD];   // transposed: xs[k][node]
    __shared__ float ws[KT][N_HID];

    int tid = threadIdx.x;
    int block_n0 = blockIdx.x * TM;
    int ty = tid >> 4;          // 0..15
    int tx = tid & 15;          // 0..15
    int n_local = ty * 8;       // 8 nodes per thread
    int j0 = tx * 4;            // 4 feats per thread

    float acc[8][4];
#pragma unroll
    for (int a = 0; a < 8; a++)
#pragma unroll
        for (int b = 0; b < 4; b++) acc[a][b] = 0.0f;

    for (int k0 = 0; k0 < N_FEAT; k0 += KT) {
        // load x tile (transposed into smem)
#pragma unroll
        for (int i = 0; i < 8; i++) {
            int idx = i * 256 + tid;      // 0..2047
            int nl = idx >> 4;            // 0..127
            int kk = idx & 15;
            int gn = block_n0 + nl;
            float v = (gn < N_NODES) ? x[(long)gn * N_FEAT + k0 + kk] : 0.0f;
            xs[kk][nl] = v;
        }
        // load W1 tile
#pragma unroll
        for (int i = 0; i < 4; i++) {
            int idx = i * 256 + tid;      // 0..1023
            int kk = idx >> 6;
            int jj = idx & 63;
            ws[kk][jj] = W1[(k0 + kk) * N_HID + jj];
        }
        __syncthreads();

#pragma unroll
        for (int kk = 0; kk < KT; kk++) {
            float4 xa = *(const float4*)&xs[kk][n_local];
            float4 xb = *(const float4*)&xs[kk][n_local + 4];
            float4 wv = *(const float4*)&ws[kk][j0];
            float xr[8] = {xa.x, xa.y, xa.z, xa.w, xb.x, xb.y, xb.z, xb.w};
            float wr[4] = {wv.x, wv.y, wv.z, wv.w};
#pragma unroll
            for (int a = 0; a < 8; a++)
#pragma unroll
                for (int b = 0; b < 4; b++)
                    acc[a][b] += xr[a] * wr[b];
        }
        __syncthreads();
    }

    float bb0 = b1[j0], bb1 = b1[j0 + 1], bb2 = b1[j0 + 2], bb3 = b1[j0 + 3];
#pragma unroll
    for (int a = 0; a < 8; a++) {
        int gn = block_n0 + n_local + a;
        if (gn < N_NODES) {
            float4 o;
            o.x = acc[a][0] + bb0;
            o.y = acc[a][1] + bb1;
            o.z = acc[a][2] + bb2;
            o.w = acc[a][3] + bb3;
            *(float4*)&g_h0[(long)gn * N_HID + j0] = o;
        }
    }
}

// ---------------------------------------------------------------------------
// SpMM1: g_h[row][f] += val * g_h0[col][f]   (one warp per edge, 2 feats/lane)
// ---------------------------------------------------------------------------
__global__ void k_spmm1(const int* __restrict__ row, const int* __restrict__ col,
                        const float* __restrict__ vals) {
    long g = (long)blockIdx.x * blockDim.x + threadIdx.x;
    int lane = (int)(g & 31);
    long e = g >> 5;
    if (e >= N_EDGES) return;
    int r = row[e], c = col[e];
    float v = vals[e];
    float a = g_h0[(long)c * N_HID + lane];
    float b = g_h0[(long)c * N_HID + lane + 32];
    atomicAdd(&g_h[(long)r * N_HID + lane],      v * a);
    atomicAdd(&g_h[(long)r * N_HID + lane + 32], v * b);
}

// ---------------------------------------------------------------------------
// GEMM2 (fused ReLU): g_h2[n][j] = sum_k relu(g_h[n][k]) * W2[k][j] + b2[j]
// 16 threads per node (one per class), broadcast float4 loads of h row
// ---------------------------------------------------------------------------
__global__ __launch_bounds__(256) void k_gemm2(const float* __restrict__ W2,
                                               const float* __restrict__ b2) {
    __shared__ float w2s[N_HID * N_CLS];   // 1024 floats
    int tid = threadIdx.x;
#pragma unroll
    for (int i = 0; i < 4; i++) w2s[i * 256 + tid] = W2[i * 256 + tid];
    __syncthreads();

    int g = blockIdx.x * 256 + tid;
    int node = g >> 4;
    int j = g & 15;
    if (node >= N_NODES) return;

    const float4* hrow = (const float4*)(g_h + (long)node * N_HID);
    float acc = 0.0f;
#pragma unroll
    for (int k4 = 0; k4 < 16; k4++) {
        float4 h4 = hrow[k4];
        float v0 = fmaxf(h4.x, 0.0f), v1 = fmaxf(h4.y, 0.0f);
        float v2 = fmaxf(h4.z, 0.0f), v3 = fmaxf(h4.w, 0.0f);
        int k = k4 * 4;
        acc += v0 * w2s[k * 16 + j];
        acc += v1 * w2s[(k + 1) * 16 + j];
        acc += v2 * w2s[(k + 2) * 16 + j];
        acc += v3 * w2s[(k + 3) * 16 + j];
    }
    g_h2[(long)node * N_CLS + j] = acc + b2[j];
}

// ---------------------------------------------------------------------------
// SpMM2: out[row][f] += val * g_h2[col][f]   (16 threads per edge)
// ---------------------------------------------------------------------------
__global__ void k_spmm2(const int* __restrict__ row, const int* __restrict__ col,
                        const float* __restrict__ vals, float* __restrict__ out) {
    long g = (long)blockIdx.x * blockDim.x + threadIdx.x;
    int f = (int)(g & 15);
    long e = g >> 4;
    if (e >= N_EDGES) return;
    int r = row[e], c = col[e];
    float v = vals[e];
    atomicAdd(&out[(long)r * N_CLS + f], v * g_h2[(long)c * N_CLS + f]);
}

// ---------------------------------------------------------------------------
// Row-wise log_softmax over 16 classes, in place on d_out
// ---------------------------------------------------------------------------
__global__ void k_lsm(float* __restrict__ out) {
    int n = blockIdx.x * blockDim.x + threadIdx.x;
    if (n >= N_NODES) return;
    float4* p = (float4*)(out + (long)n * N_CLS);
    float4 v[4];
#pragma unroll
    for (int i = 0; i < 4; i++) v[i] = p[i];
    float* f = (float*)v;
    float m = f[0];
#pragma unroll
    for (int i = 1; i < 16; i++) m = fmaxf(m, f[i]);
    float s = 0.0f;
#pragma unroll
    for (int i = 0; i < 16; i++) s += expf(f[i] - m);
    float lse = m + logf(s);
#pragma unroll
    for (int i = 0; i < 16; i++) f[i] -= lse;
#pragma unroll
    for (int i = 0; i < 4; i++) p[i] = v[i];
}

// ---------------------------------------------------------------------------
extern "C" void kernel_launch(void* const* d_in, const int* in_sizes, int n_in,
                              void* d_out, int out_size) {
    const float* x     = (const float*)d_in[0];
    const int*   arow  = (const int*)  d_in[1];
    const int*   acol  = (const int*)  d_in[2];
    const float* avals = (const float*)d_in[3];
    const float* W1    = (const float*)d_in[4];
    const float* b1    = (const float*)d_in[5];
    const float* W2    = (const float*)d_in[6];
    const float* b2    = (const float*)d_in[7];
    float* out = (float*)d_out;

    k_zero<<<(N_NODES * N_HID + 255) / 256, 256>>>(out);
    k_gemm1<<<(N_NODES + 127) / 128, 256>>>(x, W1, b1);
    {
        long total = (long)N_EDGES * 32;
        k_spmm1<<<(unsigned)((total + 255) / 256), 256>>>(arow, acol, avals);
    }
    k_gemm2<<<(N_NODES * 16 + 255) / 256, 256>>>(W2, b2);
    {
        long total = (long)N_EDGES * 16;
        k_spmm2<<<(unsigned)((total + 255) / 256), 256>>>(arow, acol, avals, out);
    }
    k_lsm<<<(N_NODES + 255) / 256, 256>>>(out);
}

// round 2
// speedup vs baseline: 1.3621x; 1.3621x over previous
#include <cuda_runtime.h>

#define N_NODES 100000
#define N_EDGES 1600000
#define N_FEAT  256
#define N_HID   64
#define N_CLS   16

#define SCAN_BLK  512
#define SCAN_NBLK ((N_NODES + SCAN_BLK - 1) / SCAN_BLK)   // 196

// ---------------- scratch (device globals: allocation-free, graph-safe) ----
__device__ float g_h0[N_NODES * N_HID];     // x@W1+b1
__device__ float g_h2[N_NODES * N_CLS];     // relu(spmm1)@W2+b2
__device__ int   g_cnt[N_NODES];            // per-row edge counts
__device__ int   g_scan[N_NODES];           // per-chunk inclusive scan
__device__ int   g_blk[SCAN_NBLK];          // chunk totals
__device__ int   g_blkoff[SCAN_NBLK];       // exclusive chunk offsets
__device__ int   g_ptr[N_NODES + 1];        // CSR row pointers
__device__ int   g_cur[N_NODES];            // scatter cursors
__device__ int2  g_edge[N_EDGES];           // {col, float_bits(val)} sorted by row

// ---------------------------------------------------------------------------
// CSR build
// ---------------------------------------------------------------------------
__global__ void k_zero_cnt() {
    int i = blockIdx.x * blockDim.x + threadIdx.x;
    if (i < N_NODES) g_cnt[i] = 0;
}

__global__ void k_hist(const int* __restrict__ row) {
    int e = blockIdx.x * blockDim.x + threadIdx.x;
    if (e < N_EDGES) atomicAdd(&g_cnt[row[e]], 1);
}

__global__ __launch_bounds__(SCAN_BLK) void k_scan1() {
    __shared__ int s[SCAN_BLK];
    int i = blockIdx.x * SCAN_BLK + threadIdx.x;
    int v = (i < N_NODES) ? g_cnt[i] : 0;
    s[threadIdx.x] = v;
    __syncthreads();
    for (int off = 1; off < SCAN_BLK; off <<= 1) {
        int t = (threadIdx.x >= off) ? s[threadIdx.x - off] : 0;
        __syncthreads();
        s[threadIdx.x] += t;
        __syncthreads();
    }
    if (i < N_NODES) g_scan[i] = s[threadIdx.x];
    if (threadIdx.x == SCAN_BLK - 1) g_blk[blockIdx.x] = s[threadIdx.x];
}

__global__ __launch_bounds__(256) void k_scan2() {
    __shared__ int s[256];
    int t = threadIdx.x;
    s[t] = (t < SCAN_NBLK) ? g_blk[t] : 0;
    __syncthreads();
    for (int off = 1; off < 256; off <<= 1) {
        int v = (t >= off) ? s[t - off] : 0;
        __syncthreads();
        s[t] += v;
        __syncthreads();
    }
    if (t < SCAN_NBLK) g_blkoff[t] = (t == 0) ? 0 : s[t - 1];
}

__global__ __launch_bounds__(SCAN_BLK) void k_scan3() {
    int i = blockIdx.x * SCAN_BLK + threadIdx.x;
    if (i < N_NODES) {
        int excl = g_scan[i] - g_cnt[i] + g_blkoff[blockIdx.x];
        g_ptr[i] = excl;
        g_cur[i] = excl;
    }
    if (i == 0) g_ptr[N_NODES] = N_EDGES;
}

__global__ void k_scatter(const int* __restrict__ row, const int* __restrict__ col,
                          const float* __restrict__ vals) {
    int e = blockIdx.x * blockDim.x + threadIdx.x;
    if (e >= N_EDGES) return;
    int r = row[e];
    int pos = atomicAdd(&g_cur[r], 1);
    g_edge[pos] = make_int2(col[e], __float_as_int(vals[e]));
}

// ---------------------------------------------------------------------------
// GEMM1: g_h0[n][j] = sum_k x[n][k] * W1[k][j] + b1[j]
// ---------------------------------------------------------------------------
__global__ __launch_bounds__(256) void k_gemm1(const float* __restrict__ x,
                                               const float* __restrict__ W1,
                                               const float* __restrict__ b1) {
    const int TM = 128, KT = 16, PAD = 4;
    __shared__ float xs[KT][TM + PAD];
    __shared__ float ws[KT][N_HID];

    int tid = threadIdx.x;
    int block_n0 = blockIdx.x * TM;
    int ty = tid >> 4;
    int tx = tid & 15;
    int n_local = ty * 8;
    int j0 = tx * 4;

    float acc[8][4];
#pragma unroll
    for (int a = 0; a < 8; a++)
#pragma unroll
        for (int b = 0; b < 4; b++) acc[a][b] = 0.0f;

    for (int k0 = 0; k0 < N_FEAT; k0 += KT) {
#pragma unroll
        for (int i = 0; i < 8; i++) {
            int idx = i * 256 + tid;
            int nl = idx >> 4;
            int kk = idx & 15;
            int gn = block_n0 + nl;
            float v = (gn < N_NODES) ? x[(long)gn * N_FEAT + k0 + kk] : 0.0f;
            xs[kk][nl] = v;
        }
#pragma unroll
        for (int i = 0; i < 4; i++) {
            int idx = i * 256 + tid;
            int kk = idx >> 6;
            int jj = idx & 63;
            ws[kk][jj] = W1[(k0 + kk) * N_HID + jj];
        }
        __syncthreads();

#pragma unroll
        for (int kk = 0; kk < KT; kk++) {
            float4 xa = *(const float4*)&xs[kk][n_local];
            float4 xb = *(const float4*)&xs[kk][n_local + 4];
            float4 wv = *(const float4*)&ws[kk][j0];
            float xr[8] = {xa.x, xa.y, xa.z, xa.w, xb.x, xb.y, xb.z, xb.w};
            float wr[4] = {wv.x, wv.y, wv.z, wv.w};
#pragma unroll
            for (int a = 0; a < 8; a++)
#pragma unroll
                for (int b = 0; b < 4; b++)
                    acc[a][b] += xr[a] * wr[b];
        }
        __syncthreads();
    }

    float bb0 = b1[j0], bb1 = b1[j0 + 1], bb2 = b1[j0 + 2], bb3 = b1[j0 + 3];
#pragma unroll
    for (int a = 0; a < 8; a++) {
        int gn = block_n0 + n_local + a;
        if (gn < N_NODES) {
            float4 o;
            o.x = acc[a][0] + bb0;
            o.y = acc[a][1] + bb1;
            o.z = acc[a][2] + bb2;
            o.w = acc[a][3] + bb3;
            *(float4*)&g_h0[(long)gn * N_HID + j0] = o;
        }
    }
}

// ---------------------------------------------------------------------------
// SpMM1 fused with ReLU + GEMM2 + bias: one warp per row.
// h[r][:] = sum_e val_e * h0[col_e][:]; g_h2[r][j] = relu(h)@W2[:,j] + b2[j]
// ---------------------------------------------------------------------------
__global__ __launch_bounds__(256) void k_spmm1f(const float* __restrict__ W2,
                                                const float* __restrict__ b2) {
    __shared__ float w2s[N_CLS][N_HID];   // transposed: w2s[j][k]
    __shared__ float b2s[N_CLS];
    int tid = threadIdx.x;
    for (int i = tid; i < N_HID * N_CLS; i += 256) {
        int k = i >> 4, j = i & 15;
        w2s[j][k] = W2[i];
    }
    if (tid < N_CLS) b2s[tid] = b2[tid];
    __syncthreads();

    int warp = tid >> 5, lane = tid & 31;
    int r = blockIdx.x * 8 + warp;
    if (r >= N_NODES) return;

    int beg = g_ptr[r], end = g_ptr[r + 1];
    float a0 = 0.0f, a1 = 0.0f;
#pragma unroll 2
    for (int e = beg; e < end; e++) {
        int2 ed = g_edge[e];
        float v = __int_as_float(ed.y);
        const float* h = g_h0 + (long)ed.x * N_HID;
        a0 += v * __ldg(h + lane);
        a1 += v * __ldg(h + lane + 32);
    }
    a0 = fmaxf(a0, 0.0f);
    a1 = fmaxf(a1, 0.0f);

    float p[N_CLS];
#pragma unroll
    for (int j = 0; j < N_CLS; j++)
        p[j] = a0 * w2s[j][lane] + a1 * w2s[j][lane + 32];
#pragma unroll
    for (int j = 0; j < N_CLS; j++) {
#pragma unroll
        for (int off = 16; off; off >>= 1)
            p[j] += __shfl_xor_sync(0xffffffffu, p[j], off);
    }
    if (lane == 0) {
        float4* o = (float4*)(g_h2 + (long)r * N_CLS);
        o[0] = make_float4(p[0] + b2s[0],  p[1] + b2s[1],  p[2] + b2s[2],  p[3] + b2s[3]);
        o[1] = make_float4(p[4] + b2s[4],  p[5] + b2s[5],  p[6] + b2s[6],  p[7] + b2s[7]);
        o[2] = make_float4(p[8] + b2s[8],  p[9] + b2s[9],  p[10] + b2s[10], p[11] + b2s[11]);
        o[3] = make_float4(p[12] + b2s[12], p[13] + b2s[13], p[14] + b2s[14], p[15] + b2s[15]);
    }
}

// ---------------------------------------------------------------------------
// SpMM2 fused with log_softmax: half-warp (16 lanes) per row, one class/lane.
// ---------------------------------------------------------------------------
__global__ __launch_bounds__(256) void k_spmm2f(float* __restrict__ out) {
    int tid = threadIdx.x;
    int warp = tid >> 5, lane = tid & 31;
    int half = lane >> 4, l16 = lane & 15;
    int r = (blockIdx.x * 8 + warp) * 2 + half;
    if (r >= N_NODES) return;

    int beg = g_ptr[r], end = g_ptr[r + 1];
    float acc = 0.0f;
#pragma unroll 2
    for (int e = beg; e < end; e++) {
        int2 ed = g_edge[e];
        acc += __int_as_float(ed.y) * __ldg(g_h2 + (long)ed.x * N_CLS + l16);
    }
    // log_softmax over the 16-lane segment
    float m = acc;
#pragma unroll
    for (int off = 8; off; off >>= 1)
        m = fmaxf(m, __shfl_xor_sync(0xffffffffu, m, off, 16));
    float s = expf(acc - m);
#pragma unroll
    for (int off = 8; off; off >>= 1)
        s += __shfl_xor_sync(0xffffffffu, s, off, 16);
    out[(long)r * N_CLS + l16] = acc - m - logf(s);
}

// ---------------------------------------------------------------------------
extern "C" void kernel_launch(void* const* d_in, const int* in_sizes, int n_in,
                              void* d_out, int out_size) {
    const float* x     = (const float*)d_in[0];
    const int*   arow  = (const int*)  d_in[1];
    const int*   acol  = (const int*)  d_in[2];
    const float* avals = (const float*)d_in[3];
    const float* W1    = (const float*)d_in[4];
    const float* b1    = (const float*)d_in[5];
    const float* W2    = (const float*)d_in[6];
    const float* b2    = (const float*)d_in[7];
    float* out = (float*)d_out;

    // CSR build
    k_zero_cnt<<<(N_NODES + 255) / 256, 256>>>();
    k_hist<<<(N_EDGES + 255) / 256, 256>>>(arow);
    k_scan1<<<SCAN_NBLK, SCAN_BLK>>>();
    k_scan2<<<1, 256>>>();
    k_scan3<<<SCAN_NBLK, SCAN_BLK>>>();
    k_scatter<<<(N_EDGES + 255) / 256, 256>>>(arow, acol, avals);

    // dense layer 1
    k_gemm1<<<(N_NODES + 127) / 128, 256>>>(x, W1, b1);

    // fused spmm1 + relu + gemm2 + bias
    k_spmm1f<<<(N_NODES + 7) / 8, 256>>>(W2, b2);

    // fused spmm2 + log_softmax
    k_spmm2f<<<(N_NODES + 15) / 16, 256>>>(out);
}

// round 3
// speedup vs baseline: 1.5456x; 1.1347x over previous
#include <cuda_runtime.h>

#define N_NODES 100000
#define N_EDGES 1600000
#define N_FEAT  256
#define N_HID   64
#define N_CLS   16

#define SCAN_BLK  512
#define SCAN_NBLK ((N_NODES + SCAN_BLK - 1) / SCAN_BLK)   // 196

// ---------------- scratch (device globals: allocation-free, graph-safe) ----
__device__ float g_h0[N_NODES * N_HID];     // x@W1+b1
__device__ float g_h2[N_NODES * N_CLS];     // relu(spmm1)@W2+b2
__device__ int   g_cnt[N_NODES];            // per-row edge counts
__device__ int   g_scan[N_NODES];           // per-chunk inclusive scan
__device__ int   g_blk[SCAN_NBLK];          // chunk totals
__device__ int   g_ptr[N_NODES + 1];        // CSR row pointers
__device__ int   g_cur[N_NODES];            // scatter cursors
__device__ int2  g_edge[N_EDGES];           // {col, float_bits(val)} sorted by row

// ---------------------------------------------------------------------------
// CSR build
// ---------------------------------------------------------------------------
__global__ void k_zero_cnt() {
    int i = blockIdx.x * blockDim.x + threadIdx.x;
    if (i < N_NODES) g_cnt[i] = 0;
}

__global__ void k_hist(const int* __restrict__ row) {
    int e = blockIdx.x * blockDim.x + threadIdx.x;
    if (e < N_EDGES) atomicAdd(&g_cnt[row[e]], 1);
}

__global__ __launch_bounds__(SCAN_BLK) void k_scan1() {
    __shared__ int s[SCAN_BLK];
    int i = blockIdx.x * SCAN_BLK + threadIdx.x;
    int v = (i < N_NODES) ? g_cnt[i] : 0;
    s[threadIdx.x] = v;
    __syncthreads();
    for (int off = 1; off < SCAN_BLK; off <<= 1) {
        int t = (threadIdx.x >= off) ? s[threadIdx.x - off] : 0;
        __syncthreads();
        s[threadIdx.x] += t;
        __syncthreads();
    }
    if (i < N_NODES) g_scan[i] = s[threadIdx.x];
    if (threadIdx.x == SCAN_BLK - 1) g_blk[blockIdx.x] = s[threadIdx.x];
}

// scan3 now also folds in the inter-block offset reduction (replaces scan2)
__global__ __launch_bounds__(SCAN_BLK) void k_scan3() {
    __shared__ int s[SCAN_BLK];
    int t = threadIdx.x;
    s[t] = (t < SCAN_NBLK && t < (int)blockIdx.x) ? g_blk[t] : 0;
    __syncthreads();
    for (int off = SCAN_BLK / 2; off; off >>= 1) {
        if (t < off) s[t] += s[t + off];
        __syncthreads();
    }
    int blkoff = s[0];
    int i = blockIdx.x * SCAN_BLK + t;
    if (i < N_NODES) {
        int excl = g_scan[i] - g_cnt[i] + blkoff;
        g_ptr[i] = excl;
        g_cur[i] = excl;
    }
    if (i == 0) g_ptr[N_NODES] = N_EDGES;
}

__global__ void k_scatter(const int* __restrict__ row, const int* __restrict__ col,
                          const float* __restrict__ vals) {
    int e = blockIdx.x * blockDim.x + threadIdx.x;
    if (e >= N_EDGES) return;
    int r = row[e];
    int pos = atomicAdd(&g_cur[r], 1);
    g_edge[pos] = make_int2(col[e], __float_as_int(vals[e]));
}

// ---------------------------------------------------------------------------
// tf32 helpers
// ---------------------------------------------------------------------------
__device__ __forceinline__ unsigned f2tf32(float f) {
    unsigned r;
    asm("cvt.rna.tf32.f32 %0, %1;" : "=r"(r) : "f"(f));
    return r;
}
__device__ __forceinline__ void mma_tf32(float c[4], unsigned a0, unsigned a1,
                                         unsigned a2, unsigned a3,
                                         unsigned b0, unsigned b1) {
    asm("mma.sync.aligned.m16n8k8.row.col.f32.tf32.tf32.f32 "
        "{%0,%1,%2,%3}, {%4,%5,%6,%7}, {%8,%9}, {%0,%1,%2,%3};"
        : "+f"(c[0]), "+f"(c[1]), "+f"(c[2]), "+f"(c[3])
        : "r"(a0), "r"(a1), "r"(a2), "r"(a3), "r"(b0), "r"(b1));
}

// ---------------------------------------------------------------------------
// GEMM1 (tensor core, tf32): g_h0[n][j] = sum_k x[n][k]*W1[k][j] + b1[j]
// Block: 256 thr (8 warps). Tile: M=128 nodes x N=64, K-chunks of 32.
// Warp w computes rows [w*16, w*16+16) x all 64 cols: 8 n-tiles of m16n8k8.
// ---------------------------------------------------------------------------
__global__ __launch_bounds__(256) void k_gemm1(const float* __restrict__ x,
                                               const float* __restrict__ W1,
                                               const float* __restrict__ b1) {
    __shared__ unsigned xs[128][36];   // tf32 bits, pad 36 -> conflict-free frags
    __shared__ unsigned ws[32][68];    // tf32 bits
    __shared__ float b1s[64];

    int tid = threadIdx.x;
    int n0 = blockIdx.x * 128;
    if (tid < 64) b1s[tid] = b1[tid];

    int warp = tid >> 5, lane = tid & 31;
    int qr = lane >> 2, qc = lane & 3;

    float c[8][4];
#pragma unroll
    for (int i = 0; i < 8; i++)
#pragma unroll
        for (int j = 0; j < 4; j++) c[i][j] = 0.0f;

    // x-load mapping: row = tid/2, 16 cols starting at (tid&1)*16
    int xr = tid >> 1, xc = (tid & 1) * 16;
    // W-load mapping: row k = tid/8, 8 cols starting at (tid&7)*8
    int wk = tid >> 3, wc = (tid & 7) * 8;

    for (int k0 = 0; k0 < N_FEAT; k0 += 32) {
        __syncthreads();   // previous iteration's reads done before overwrite
        long gn = n0 + xr;
        if (gn < N_NODES) {
            const float4* xp = (const float4*)(x + gn * N_FEAT + k0 + xc);
#pragma unroll
            for (int i = 0; i < 4; i++) {
                float4 v = xp[i];
                xs[xr][xc + i * 4 + 0] = f2tf32(v.x);
                xs[xr][xc + i * 4 + 1] = f2tf32(v.y);
                xs[xr][xc + i * 4 + 2] = f2tf32(v.z);
                xs[xr][xc + i * 4 + 3] = f2tf32(v.w);
            }
        } else {
#pragma unroll
            for (int i = 0; i < 16; i++) xs[xr][xc + i] = 0u;
        }
        {
            const float4* wp = (const float4*)(W1 + (long)(k0 + wk) * N_HID + wc);
#pragma unroll
            for (int i = 0; i < 2; i++) {
                float4 v = wp[i];
                ws[wk][wc + i * 4 + 0] = f2tf32(v.x);
                ws[wk][wc + i * 4 + 1] = f2tf32(v.y);
                ws[wk][wc + i * 4 + 2] = f2tf32(v.z);
                ws[wk][wc + i * 4 + 3] = f2tf32(v.w);
            }
        }
        __syncthreads();

        int m = warp * 16 + qr;
#pragma unroll
        for (int ks = 0; ks < 4; ks++) {
            int kq = ks * 8 + qc;
            unsigned a0 = xs[m][kq];
            unsigned a1 = xs[m + 8][kq];
            unsigned a2 = xs[m][kq + 4];
            unsigned a3 = xs[m + 8][kq + 4];
#pragma unroll
            for (int nt = 0; nt < 8; nt++) {
                unsigned b0 = ws[kq][nt * 8 + qr];
                unsigned b1v = ws[kq + 4][nt * 8 + qr];
                mma_tf32(c[nt], a0, a1, a2, a3, b0, b1v);
            }
        }
    }

    int row0 = n0 + warp * 16 + qr;
    int row1 = row0 + 8;
    int col0 = qc * 2;
#pragma unroll
    for (int nt = 0; nt < 8; nt++) {
        int cc = nt * 8 + col0;
        if (row0 < N_NODES) {
            float2 o = make_float2(c[nt][0] + b1s[cc], c[nt][1] + b1s[cc + 1]);
            *(float2*)&g_h0[(long)row0 * N_HID + cc] = o;
        }
        if (row1 < N_NODES) {
            float2 o = make_float2(c[nt][2] + b1s[cc], c[nt][3] + b1s[cc + 1]);
            *(float2*)&g_h0[(long)row1 * N_HID + cc] = o;
        }
    }
}

// ---------------------------------------------------------------------------
// SpMM1 fused with ReLU + GEMM2 + bias: one warp per row.
// ---------------------------------------------------------------------------
__global__ __launch_bounds__(256) void k_spmm1f(const float* __restrict__ W2,
                                                const float* __restrict__ b2) {
    __shared__ float w2s[N_CLS][N_HID];   // transposed: w2s[j][k]
    __shared__ float b2s[N_CLS];
    int tid = threadIdx.x;
    for (int i = tid; i < N_HID * N_CLS; i += 256) {
        int k = i >> 4, j = i & 15;
        w2s[j][k] = W2[i];
    }
    if (tid < N_CLS) b2s[tid] = b2[tid];
    __syncthreads();

    int warp = tid >> 5, lane = tid & 31;
    int r = blockIdx.x * 8 + warp;
    if (r >= N_NODES) return;

    int beg = g_ptr[r], end = g_ptr[r + 1];
    float a0 = 0.0f, a1 = 0.0f;
#pragma unroll 2
    for (int e = beg; e < end; e++) {
        int2 ed = g_edge[e];
        float v = __int_as_float(ed.y);
        const float* h = g_h0 + (long)ed.x * N_HID;
        a0 += v * __ldg(h + lane);
        a1 += v * __ldg(h + lane + 32);
    }
    a0 = fmaxf(a0, 0.0f);
    a1 = fmaxf(a1, 0.0f);

    float p[N_CLS];
#pragma unroll
    for (int j = 0; j < N_CLS; j++)
        p[j] = a0 * w2s[j][lane] + a1 * w2s[j][lane + 32];
#pragma unroll
    for (int j = 0; j < N_CLS; j++) {
#pragma unroll
        for (int off = 16; off; off >>= 1)
            p[j] += __shfl_xor_sync(0xffffffffu, p[j], off);
    }
    if (lane == 0) {
        float4* o = (float4*)(g_h2 + (long)r * N_CLS);
        o[0] = make_float4(p[0] + b2s[0],  p[1] + b2s[1],  p[2] + b2s[2],  p[3] + b2s[3]);
        o[1] = make_float4(p[4] + b2s[4],  p[5] + b2s[5],  p[6] + b2s[6],  p[7] + b2s[7]);
        o[2] = make_float4(p[8] + b2s[8],  p[9] + b2s[9],  p[10] + b2s[10], p[11] + b2s[11]);
        o[3] = make_float4(p[12] + b2s[12], p[13] + b2s[13], p[14] + b2s[14], p[15] + b2s[15]);
    }
}

// ---------------------------------------------------------------------------
// SpMM2 fused with log_softmax: half-warp (16 lanes) per row, one class/lane.
// ---------------------------------------------------------------------------
__global__ __launch_bounds__(256) void k_spmm2f(float* __restrict__ out) {
    int tid = threadIdx.x;
    int warp = tid >> 5, lane = tid & 31;
    int half = lane >> 4, l16 = lane & 15;
    int r = (blockIdx.x * 8 + warp) * 2 + half;
    if (r >= N_NODES) return;

    int beg = g_ptr[r], end = g_ptr[r + 1];
    float acc = 0.0f;
#pragma unroll 2
    for (int e = beg; e < end; e++) {
        int2 ed = g_edge[e];
        acc += __int_as_float(ed.y) * __ldg(g_h2 + (long)ed.x * N_CLS + l16);
    }
    float m = acc;
#pragma unroll
    for (int off = 8; off; off >>= 1)
        m = fmaxf(m, __shfl_xor_sync(0xffffffffu, m, off, 16));
    float s = expf(acc - m);
#pragma unroll
    for (int off = 8; off; off >>= 1)
        s += __shfl_xor_sync(0xffffffffu, s, off, 16);
    out[(long)r * N_CLS + l16] = acc - m - logf(s);
}

// ---------------------------------------------------------------------------
extern "C" void kernel_launch(void* const* d_in, const int* in_sizes, int n_in,
                              void* d_out, int out_size) {
    const float* x     = (const float*)d_in[0];
    const int*   arow  = (const int*)  d_in[1];
    const int*   acol  = (const int*)  d_in[2];
    const float* avals = (const float*)d_in[3];
    const float* W1    = (const float*)d_in[4];
    const float* b1    = (const float*)d_in[5];
    const float* W2    = (const float*)d_in[6];
    const float* b2    = (const float*)d_in[7];
    float* out = (float*)d_out;

    // CSR build
    k_zero_cnt<<<(N_NODES + 255) / 256, 256>>>();
    k_hist<<<(N_EDGES + 255) / 256, 256>>>(arow);
    k_scan1<<<SCAN_NBLK, SCAN_BLK>>>();
    k_scan3<<<SCAN_NBLK, SCAN_BLK>>>();
    k_scatter<<<(N_EDGES + 255) / 256, 256>>>(arow, acol, avals);

    // dense layer 1 (tf32 tensor cores)
    k_gemm1<<<(N_NODES + 127) / 128, 256>>>(x, W1, b1);

    // fused spmm1 + relu + gemm2 + bias
    k_spmm1f<<<(N_NODES + 7) / 8, 256>>>(W2, b2);

    // fused spmm2 + log_softmax
    k_spmm2f<<<(N_NODES + 15) / 16, 256>>>(out);
}